// round 13
// baseline (speedup 1.0000x reference)
#include <cuda_runtime.h>
#include <cuda_fp16.h>

#define B_   2
#define G_   512
#define K_   32
#define D_   128
#define N_   16384
#define L_   50
#define S_   2
#define TPB  256
#define SX   136     // half stride for X / q / k rows
#define SV   40      // half stride for vT rows (d-major)
#define SA   40      // half stride for attn rows
#define SSC  36      // f32 stride for scores
#define SP   52      // f32 stride for P

typedef unsigned long long ull;
typedef unsigned int u32;

// fragment-order fp16 (half2-packed) weights, rebuilt by repack_kernel each launch
// qkvR layout (R7): [st][k16][w][jp(3)][128] -- uint4 per lane covers tile pair (2jp, 2jp+1)
__device__ u32 qkvR[2 * 8 * 8 * 3 * 128];   // 49152 u32
__device__ u32 trR [3 * 8 * 8 * 128];       // 24576 u32
__device__ u32 tbR [2 * 3 * 8 * 7 * 64];    // 21504 u32

__device__ __forceinline__ u32 packh(float a, float b) {
    __half2 h = __floats2half2_rn(a, b);
    return *(u32*)&h;
}
__device__ __forceinline__ ull pack2(float x, float y) {
    ull r; asm("mov.b64 %0, {%1, %2};" : "=l"(r) : "f"(x), "f"(y)); return r;
}
__device__ __forceinline__ void mma16(float* c, const u32* a, const u32* b) {
    asm("mma.sync.aligned.m16n8k16.row.col.f32.f16.f16.f32 "
        "{%0,%1,%2,%3},{%4,%5,%6,%7},{%8,%9},{%0,%1,%2,%3};"
        : "+f"(c[0]), "+f"(c[1]), "+f"(c[2]), "+f"(c[3])
        : "r"(a[0]), "r"(a[1]), "r"(a[2]), "r"(a[3]), "r"(b[0]), "r"(b[1]));
}
// A fragment (16x16 f16) via ldmatrix.x4 from row-major half smem
__device__ __forceinline__ void ldsmA(u32* a, const __half* S, int strideH,
                                      int mr, int kc, int lane) {
    const __half* p = S + (mr + (lane & 15)) * strideH + kc + ((lane >> 4) << 3);
    u32 sa_ = (u32)__cvta_generic_to_shared((void*)p);
    asm volatile("ldmatrix.sync.aligned.m8n8.x4.shared.b16 {%0,%1,%2,%3}, [%4];"
                 : "=r"(a[0]), "=r"(a[1]), "=r"(a[2]), "=r"(a[3]) : "r"(sa_));
}
// B fragment from n-major half smem: B[k][n] at S[n*strideH + k] (k contiguous)
__device__ __forceinline__ void ldBh(u32* b, const __half* S, int strideH,
                                     int nc, int kc, int lane) {
    const u32* p = (const u32*)(S + (nc + (lane >> 2)) * strideH + kc) + (lane & 3);
    b[0] = p[0]; b[1] = p[4];
}

// ---------------- repack: f32 weights -> fragment-order half2 ----------------
__global__ void repack_kernel(const float* __restrict__ qkv_w,
                              const float* __restrict__ trans_w,
                              const float* __restrict__ tx,
                              const float* __restrict__ ty,
                              const float* __restrict__ tz)
{
    int e = blockIdx.x * TPB + threadIdx.x;
    if (e < 49152) {                                    // qkv (R7 uint4-pair layout)
        int qq = e & 3, lane = (e >> 2) & 31;
        int f = e >> 7;
        int p   = f % 3;  f /= 3;
        int w   = f % 8;  f /= 8;
        int k16 = f % 8;
        int st  = f / 8;
        int tile = p * 2 + (qq >> 1), breg = qq & 1;
        int col  = w * 48 + tile * 8 + (lane >> 2);
        int krow = k16 * 16 + 2 * (lane & 3) + 8 * breg;
        const float* W = qkv_w + st * 49152;
        qkvR[e] = packh(W[krow * 384 + col], W[(krow + 1) * 384 + col]);
    } else if (e < 73728) {                             // trans
        int e2 = e - 49152;
        int qq = e2 & 3, lane = (e2 >> 2) & 31;
        int f = e2 >> 7;
        int w   = f % 8;  f /= 8;
        int k16 = f % 8;
        int blk = f / 8;
        int j = qq >> 1, breg = qq & 1;
        int col  = w * 16 + j * 8 + (lane >> 2);
        int krow = k16 * 16 + 2 * (lane & 3) + 8 * breg;
        const float* W = trans_w + blk * 16384;
        trR[e2] = packh(W[krow * 128 + col], W[(krow + 1) * 128 + col]);
    } else if (e < 95232) {                             // tables
        int e3 = e - 73728;
        int qq = e3 & 1, lane = (e3 >> 1) & 31;
        int f = e3 >> 6;
        int n   = f % 7;  f /= 7;
        int k16 = f % 8;  f /= 8;
        int t   = f % 3;
        int st  = f / 3;
        const float* T = (t == 0 ? tx : (t == 1 ? ty : tz)) + (st * 3 + 1) * L_ * D_;
        int nn = n * 8 + (lane >> 2);       // <=55, in-bounds of table alloc; never indexed >49
        int kk = k16 * 16 + 2 * (lane & 3) + 8 * qq;
        tbR[e3] = packh(T[nn * D_ + kk], T[nn * D_ + kk + 1]);
    }
}

// ---------------- shared memory (55808 B -> 4 CTAs/SM) ----------------
struct __align__(16) Smem {
    float  Pf[3 * K_ * SP];  // P f32 [3][32][52]; first 8704B alias X/FO half[32][136]; H at end
    __half q [K_ * SX];      // fp16
    __half k [K_ * SX];      // fp16
    __half vT[D_ * SV];      // v transposed [d][j], fp16
    float  sc[K_ * SSC];     // raw scores f32
    __half at[K_ * SA];      // attn fp16
    float  cx[K_], cy[K_], cz[K_];
    float  pooled[D_];
    int    gidx[K_];
};

// ht += X @ W-block (repacked half2); warp w owns cols [16w,16w+16)  (standalone, block2 only)
__device__ __forceinline__ void trans_mma(const __half* __restrict__ X,
                                          const u32* __restrict__ Rb,
                                          float ht[2][2][4], int w, int lane)
{
#pragma unroll
    for (int k16 = 0; k16 < 8; k16++) {
        uint4 vv = *(const uint4*)(Rb + ((k16 * 8 + w) << 7) + lane * 4);
        u32 b0[2] = {vv.x, vv.y}, b1[2] = {vv.z, vv.w};
        u32 a0[4], a1[4];
        ldsmA(a0, X, SX, 0,  k16 * 16, lane);
        ldsmA(a1, X, SX, 16, k16 * 16, lane);
        mma16(ht[0][0], a0, b0); mma16(ht[1][0], a1, b0);
        mma16(ht[0][1], a0, b1); mma16(ht[1][1], a1, b1);
    }
}

// one qkv column pass: j-tiles [J0, J0+3) of warp w's 6 (JN=3: 24 accums).
// B loads stay uint4-block-friendly: J0=0 -> uint4(jp0)+uint2(jp1 lo); J0=3 -> uint2(jp1 hi)+uint4(jp2)
// DOHT: also accumulate ht += X @ trans_w_block (A-fragments shared -- free loads)
template<int J0, bool DOHT>
__device__ __forceinline__ void qkv_pass(Smem& s, const __half* __restrict__ XU,
                                         const float* __restrict__ bb,
                                         int st, int w, int lane,
                                         float ht[2][2][4], const u32* __restrict__ Rb)
{
    const int nw = w * 48;
    float c[2][3][4];
#pragma unroll
    for (int j = 0; j < 3; j++) {
        float b0 = bb[nw + (J0 + j) * 8 + 2 * (lane & 3)];
        float b1 = bb[nw + (J0 + j) * 8 + 2 * (lane & 3) + 1];
        c[0][j][0] = b0; c[0][j][1] = b1; c[0][j][2] = b0; c[0][j][3] = b1;
        c[1][j][0] = b0; c[1][j][1] = b1; c[1][j][2] = b0; c[1][j][3] = b1;
    }
#pragma unroll
    for (int k16 = 0; k16 < 8; k16++) {
        const u32* rp = qkvR + (((st * 8 + k16) * 8 + w) * 3) * 128 + lane * 4;
        u32 bv[3][2];
        if (J0 == 0) {
            uint4 v = *(const uint4*)(rp);
            uint2 u = *(const uint2*)(rp + 128);
            bv[0][0] = v.x; bv[0][1] = v.y;
            bv[1][0] = v.z; bv[1][1] = v.w;
            bv[2][0] = u.x; bv[2][1] = u.y;
        } else {
            uint2 u = *(const uint2*)(rp + 128 + 2);
            uint4 v = *(const uint4*)(rp + 256);
            bv[0][0] = u.x; bv[0][1] = u.y;
            bv[1][0] = v.x; bv[1][1] = v.y;
            bv[2][0] = v.z; bv[2][1] = v.w;
        }
        uint4 tv;
        if (DOHT) tv = *(const uint4*)(Rb + ((k16 * 8 + w) << 7) + lane * 4);
        u32 a0[4], a1[4];
        ldsmA(a0, XU, SX, 0,  k16 * 16, lane);
        ldsmA(a1, XU, SX, 16, k16 * 16, lane);
#pragma unroll
        for (int j = 0; j < 3; j++) {
            mma16(c[0][j], a0, bv[j]);
            mma16(c[1][j], a1, bv[j]);
        }
        if (DOHT) {
            u32 t0[2] = {tv.x, tv.y}, t1[2] = {tv.z, tv.w};
            mma16(ht[0][0], a0, t0); mma16(ht[1][0], a1, t0);
            mma16(ht[0][1], a0, t1); mma16(ht[1][1], a1, t1);
        }
    }
    // writeback fp16: cols 0-127 -> q, 128-255 -> k, 256-383 -> vT (transposed)
#pragma unroll
    for (int m = 0; m < 2; m++)
#pragma unroll
        for (int j = 0; j < 3; j++) {
            int col = nw + (J0 + j) * 8 + 2 * (lane & 3);
            int row = (lane >> 2) + m * 16;
            float* c4 = c[m][j];
            if (col < 128) {
                *(u32*)(s.q + row * SX + col)       = packh(c4[0], c4[1]);
                *(u32*)(s.q + (row + 8) * SX + col) = packh(c4[2], c4[3]);
            } else if (col < 256) {
                int cc = col - 128;
                *(u32*)(s.k + row * SX + cc)        = packh(c4[0], c4[1]);
                *(u32*)(s.k + (row + 8) * SX + cc)  = packh(c4[2], c4[3]);
            } else {
                int cc = col - 256;
                s.vT[cc * SV + row]           = __float2half_rn(c4[0]);
                s.vT[(cc + 1) * SV + row]     = __float2half_rn(c4[1]);
                s.vT[cc * SV + row + 8]       = __float2half_rn(c4[2]);
                s.vT[(cc + 1) * SV + row + 8] = __float2half_rn(c4[3]);
            }
        }
}

__global__ void __launch_bounds__(TPB, 4)
voxel_encoder_kernel(const float* __restrict__ inputs,
                     const float* __restrict__ coordinates,
                     const float* __restrict__ qkv_b,
                     const float* __restrict__ trans_b,
                     const float* __restrict__ ln_g,
                     const float* __restrict__ ln_b,
                     const int*   __restrict__ groups,
                     float* __restrict__ out,
                     float* __restrict__ ret)
{
    extern __shared__ __align__(16) char smem_raw[];
    Smem& s = *reinterpret_cast<Smem*>(smem_raw);

    const int tid  = threadIdx.x;
    const int w    = tid >> 5;
    const int lane = tid & 31;
    const int bg   = blockIdx.x;
    const int b    = bg / G_;
    const int g    = bg % G_;
    const int c0   = lane * 4;

    __half* XU = (__half*)s.Pf;               // X / FO overlay P region
    float*  P0 = s.Pf;
    float*  P1 = s.Pf + K_ * SP;
    float*  P2 = s.Pf + 2 * K_ * SP;

    // ---- gather indices + coordinates ----
    if (tid < K_) {
        int p = groups[bg * K_ + tid];
        s.gidx[tid] = p;
        const float* c = coordinates + ((long long)b * N_ + p) * 3;
        s.cx[tid] = c[0]; s.cy[tid] = c[1]; s.cz[tid] = c[2];
    }
    __syncthreads();

    // ---- gather features -> XU as fp16 ----
#pragma unroll
    for (int rr = 0; rr < 4; rr++) {
        int e = tid + TPB * rr;
        int row = e >> 5, c4 = e & 31;
        float4 val = *(const float4*)(inputs + ((long long)b * N_ + s.gidx[row]) * D_ + c4 * 4);
        uint2 hv; hv.x = packh(val.x, val.y); hv.y = packh(val.z, val.w);
        *(uint2*)(XU + row * SX + c4 * 4) = hv;
    }
    __syncthreads();

    // ---- trans accumulator in registers: warp w cols [16w,16w+16) ----
    float ht[2][2][4];
#pragma unroll
    for (int j = 0; j < 2; j++) {
        int col = w * 16 + j * 8 + 2 * (lane & 3);
        float b0 = trans_b[col], b1 = trans_b[col + 1];
        ht[0][j][0] = b0; ht[0][j][1] = b1; ht[0][j][2] = b0; ht[0][j][3] = b1;
        ht[1][j][0] = b0; ht[1][j][1] = b1; ht[1][j][2] = b0; ht[1][j][3] = b1;
    }

    // ================= attention stages =================
    // trans block st is FUSED into qkv stage-st pass2 (same A-fragments).
    for (int st = 0; st < S_; st++) {
        // ---------- qkv: two JN=3 column passes; pass2 also ht += X @ W_block(st) ----------
        {
            const float* bb = qkv_b + st * 3 * D_;
            qkv_pass<0, false>(s, XU, bb, st, w, lane, ht, nullptr);
            qkv_pass<3, true >(s, XU, bb, st, w, lane, ht, trR + st * 8 * 8 * 128);
            __syncthreads();
        }

        // ---------- P projections (warps 0-6) + scores (warp 7) ----------
        {
            if (w < 7) {
                float pc[3][2][4];
#pragma unroll
                for (int u = 0; u < 3; u++)
#pragma unroll
                    for (int m = 0; m < 2; m++)
#pragma unroll
                        for (int r = 0; r < 4; r++) pc[u][m][r] = 0.f;
#pragma unroll
                for (int k16 = 0; k16 < 8; k16++) {
                    u32 bv[3][2];
#pragma unroll
                    for (int u = 0; u < 3; u++) {
                        int tile = w * 3 + u;
                        int tt = tile / 7, n = tile % 7;
                        uint2 vv = *(const uint2*)(tbR +
                            ((((st * 3 + tt) * 8 + k16) * 7 + n) << 6) + lane * 2);
                        bv[u][0] = vv.x; bv[u][1] = vv.y;
                    }
                    u32 a0[4], a1[4];
                    ldsmA(a0, s.k, SX, 0,  k16 * 16, lane);
                    ldsmA(a1, s.k, SX, 16, k16 * 16, lane);
#pragma unroll
                    for (int u = 0; u < 3; u++) {
                        mma16(pc[u][0], a0, bv[u]);
                        mma16(pc[u][1], a1, bv[u]);
                    }
                }
#pragma unroll
                for (int u = 0; u < 3; u++) {
                    int tile = w * 3 + u;
                    int tt = tile / 7, nc = (tile % 7) * 8;
                    float* Pb = s.Pf + tt * K_ * SP;
                    int col = nc + 2 * (lane & 3);
                    bool ok = (col < SP - 1);        // clip tile 6 cols 52-55 (never read)
#pragma unroll
                    for (int m = 0; m < 2; m++) {
                        int row = (lane >> 2) + m * 16;
                        if (ok) {
                            *(ull*)&Pb[row * SP + col]       = pack2(pc[u][m][0], pc[u][m][1]);
                            *(ull*)&Pb[(row + 8) * SP + col] = pack2(pc[u][m][2], pc[u][m][3]);
                        }
                    }
                }
            } else {
                float scv[4][2][4];
#pragma unroll
                for (int n = 0; n < 4; n++)
#pragma unroll
                    for (int m = 0; m < 2; m++)
#pragma unroll
                        for (int r = 0; r < 4; r++) scv[n][m][r] = 0.f;
#pragma unroll
                for (int k16 = 0; k16 < 8; k16++) {
                    u32 a0[4], a1[4];
                    ldsmA(a0, s.q, SX, 0,  k16 * 16, lane);
                    ldsmA(a1, s.q, SX, 16, k16 * 16, lane);
#pragma unroll
                    for (int n = 0; n < 4; n++) {
                        u32 bv[2];
                        ldBh(bv, s.k, SX, n * 8, k16 * 16, lane);
                        mma16(scv[n][0], a0, bv);
                        mma16(scv[n][1], a1, bv);
                    }
                }
#pragma unroll
                for (int n = 0; n < 4; n++)
#pragma unroll
                    for (int m = 0; m < 2; m++) {
                        int col = n * 8 + 2 * (lane & 3);
                        int row = (lane >> 2) + m * 16;
                        *(ull*)&s.sc[row * SSC + col]       = pack2(scv[n][m][0], scv[n][m][1]);
                        *(ull*)&s.sc[(row + 8) * SSC + col] = pack2(scv[n][m][2], scv[n][m][3]);
                    }
            }
            __syncthreads();
        }

        // ---------- bias gather + softmax (warp w rows 4w..4w+3) ----------
        {
            const int i0 = w * 4;
            float cxj = s.cx[lane], cyj = s.cy[lane], czj = s.cz[lane];
#pragma unroll
            for (int r = 0; r < 4; r++) {
                int i = i0 + r;
                float dx = s.cx[i] - cxj;
                float dy = s.cy[i] - cyj;
                float dz = s.cz[i] - czj;
                int ix = min(max((int)floorf((dx + 0.25f) / 0.01f), 0), L_ - 1);
                int iy = min(max((int)floorf((dy + 0.25f) / 0.01f), 0), L_ - 1);
                int iz = min(max((int)floorf((dz + 0.25f) / 0.01f), 0), L_ - 1);
                float scr = (s.sc[i * SSC + lane]
                             + P0[i * SP + ix] + P1[i * SP + iy] + P2[i * SP + iz])
                            * 0.08838834764831843f;   // 1/sqrt(128)
                float mx = scr;
#pragma unroll
                for (int o = 16; o; o >>= 1) mx = fmaxf(mx, __shfl_xor_sync(0xffffffffu, mx, o));
                float e = __expf(scr - mx);
                float sum = e;
#pragma unroll
                for (int o = 16; o; o >>= 1) sum += __shfl_xor_sync(0xffffffffu, sum, o);
                s.at[i * SA + lane] = __float2half_rn(e * (1.0f / sum));
            }
        }
        __syncthreads();

        // ---------- f = attn @ v -> XU (next-stage X / final f2) ----------
        {
            float fc[2][2][4];
#pragma unroll
            for (int m = 0; m < 2; m++)
#pragma unroll
                for (int j = 0; j < 2; j++)
#pragma unroll
                    for (int r = 0; r < 4; r++) fc[m][j][r] = 0.f;
#pragma unroll
            for (int k16 = 0; k16 < 2; k16++) {
                int kc = k16 * 16;
                u32 a0[4], a1[4];
                ldsmA(a0, s.at, SA, 0,  kc, lane);
                ldsmA(a1, s.at, SA, 16, kc, lane);
#pragma unroll
                for (int j = 0; j < 2; j++) {
                    u32 bv[2];
                    ldBh(bv, s.vT, SV, w * 16 + j * 8, kc, lane);
                    mma16(fc[0][j], a0, bv);
                    mma16(fc[1][j], a1, bv);
                }
            }
#pragma unroll
            for (int m = 0; m < 2; m++)
#pragma unroll
                for (int j = 0; j < 2; j++) {
                    int col = w * 16 + j * 8 + 2 * (lane & 3);
                    int row = (lane >> 2) + m * 16;
                    *(u32*)(XU + row * SX + col)       = packh(fc[m][j][0], fc[m][j][1]);
                    *(u32*)(XU + (row + 8) * SX + col) = packh(fc[m][j][2], fc[m][j][3]);
                }
        }
        __syncthreads();
    }

    // ---- final trans block2 on f2 (no qkv consumes f2 -> standalone) ----
    trans_mma(XU, trR + 2 * 8 * 8 * 128, ht, w, lane);
    __syncthreads();

    // ---- dump trans accumulator f32 -> H (reuse P region; X dead) ----
    float* H = s.Pf;
#pragma unroll
    for (int m = 0; m < 2; m++)
#pragma unroll
        for (int j = 0; j < 2; j++) {
            int col = w * 16 + j * 8 + 2 * (lane & 3);
            int row = (lane >> 2) + m * 16;
            *(ull*)&H[row * 128 + col]       = pack2(ht[m][j][0], ht[m][j][1]);
            *(ull*)&H[(row + 8) * 128 + col] = pack2(ht[m][j][2], ht[m][j][3]);
        }
    __syncthreads();

    // ================= LayerNorm + ReLU =================
    {
        const int i0 = w * 4;
        float4 g4 = *(const float4*)(ln_g + c0);
        float4 b4 = *(const float4*)(ln_b + c0);
#pragma unroll
        for (int r = 0; r < 4; r++) {
            int i = i0 + r;
            float4 h = *(const float4*)&H[i * 128 + c0];
            float s1 = h.x + h.y + h.z + h.w;
            float s2 = h.x * h.x + h.y * h.y + h.z * h.z + h.w * h.w;
#pragma unroll
            for (int o = 16; o; o >>= 1) {
                s1 += __shfl_xor_sync(0xffffffffu, s1, o);
                s2 += __shfl_xor_sync(0xffffffffu, s2, o);
            }
            float mu   = s1 * (1.0f / 128.0f);
            float var  = s2 * (1.0f / 128.0f) - mu * mu;
            float rstd = rsqrtf(var + 1e-5f);
            h.x = fmaxf((h.x - mu) * rstd * g4.x + b4.x, 0.0f);
            h.y = fmaxf((h.y - mu) * rstd * g4.y + b4.y, 0.0f);
            h.z = fmaxf((h.z - mu) * rstd * g4.z + b4.z, 0.0f);
            h.w = fmaxf((h.w - mu) * rstd * g4.w + b4.w, 0.0f);
            *(float4*)&H[i * 128 + c0] = h;
        }
    }
    __syncthreads();

    // ================= max-pool + outputs =================
    if (tid < D_) {
        float m = H[tid];
#pragma unroll
        for (int i = 1; i < K_; i++) m = fmaxf(m, H[i * 128 + tid]);
        s.pooled[tid] = m;
        int mm = g >> 6, nn = (g >> 3) & 7, tt = g & 7;
        int p = (tt << 6) + (nn << 3) + mm;          // transpose(0,3,2,1,4)
        out[((long long)b * G_ + p) * D_ + tid] = m;
    }
    __syncthreads();

#pragma unroll
    for (int rr = 0; rr < 4; rr++) {
        int e = tid + TPB * rr;
        int row = e >> 5, c4 = e & 31;
        float4 val = *(const float4*)&s.pooled[c4 * 4];
        *(float4*)(ret + ((long long)b * N_ + s.gidx[row]) * D_ + c4 * 4) = val;
    }
}

extern "C" void kernel_launch(void* const* d_in, const int* in_sizes, int n_in,
                              void* d_out, int out_size)
{
    const float* inputs      = (const float*)d_in[0];
    const float* coordinates = (const float*)d_in[1];
    const float* qkv_w       = (const float*)d_in[2];
    const float* qkv_b       = (const float*)d_in[3];
    const float* table_x     = (const float*)d_in[4];
    const float* table_y     = (const float*)d_in[5];
    const float* table_z     = (const float*)d_in[6];
    const float* trans_w     = (const float*)d_in[7];
    const float* trans_b     = (const float*)d_in[8];
    const float* ln_g        = (const float*)d_in[9];
    const float* ln_b        = (const float*)d_in[10];
    const int*   groups      = (const int*)d_in[11];

    float* out = (float*)d_out;                      // [B, 512, 128]
    float* ret = out + (size_t)B_ * G_ * D_;         // [B, 16384, 128]

    repack_kernel<<<(95232 + TPB - 1) / TPB, TPB>>>(
        qkv_w, trans_w, table_x, table_y, table_z);

    cudaFuncSetAttribute(voxel_encoder_kernel,
                         cudaFuncAttributeMaxDynamicSharedMemorySize,
                         (int)sizeof(Smem));

    voxel_encoder_kernel<<<B_ * G_, TPB, sizeof(Smem)>>>(
        inputs, coordinates, qkv_b, trans_b, ln_g, ln_b, groups, out, ret);
}

// round 14
// speedup vs baseline: 1.2971x; 1.2971x over previous
#include <cuda_runtime.h>
#include <cuda_fp16.h>

#define B_   2
#define G_   512
#define K_   32
#define D_   128
#define N_   16384
#define L_   50
#define S_   2
#define TPB  256
#define SX   136     // half stride for X / q / k rows
#define SV   40      // half stride for vT rows (d-major)
#define SA   40      // half stride for attn rows
#define SSC  36      // f32 stride for scores
#define SP   52      // f32 stride for P

typedef unsigned long long ull;
typedef unsigned int u32;

// fragment-order fp16 (half2-packed) weights, rebuilt by repack_kernel each launch
__device__ u32 qkvR[2 * 8 * 8 * 3 * 128];   // 49152 u32
__device__ u32 trR [3 * 8 * 8 * 128];       // 24576 u32
__device__ u32 tbR [2 * 3 * 8 * 7 * 64];    // 21504 u32

__device__ __forceinline__ u32 packh(float a, float b) {
    __half2 h = __floats2half2_rn(a, b);
    return *(u32*)&h;
}
__device__ __forceinline__ ull pack2(float x, float y) {
    ull r; asm("mov.b64 %0, {%1, %2};" : "=l"(r) : "f"(x), "f"(y)); return r;
}
__device__ __forceinline__ void mma16(float* c, const u32* a, const u32* b) {
    asm("mma.sync.aligned.m16n8k16.row.col.f32.f16.f16.f32 "
        "{%0,%1,%2,%3},{%4,%5,%6,%7},{%8,%9},{%0,%1,%2,%3};"
        : "+f"(c[0]), "+f"(c[1]), "+f"(c[2]), "+f"(c[3])
        : "r"(a[0]), "r"(a[1]), "r"(a[2]), "r"(a[3]), "r"(b[0]), "r"(b[1]));
}
// A fragment (16x16 f16) via ldmatrix.x4 from row-major half smem
__device__ __forceinline__ void ldsmA(u32* a, const __half* S, int strideH,
                                      int mr, int kc, int lane) {
    const __half* p = S + (mr + (lane & 15)) * strideH + kc + ((lane >> 4) << 3);
    u32 sa_ = (u32)__cvta_generic_to_shared((void*)p);
    asm volatile("ldmatrix.sync.aligned.m8n8.x4.shared.b16 {%0,%1,%2,%3}, [%4];"
                 : "=r"(a[0]), "=r"(a[1]), "=r"(a[2]), "=r"(a[3]) : "r"(sa_));
}
// B fragment from n-major half smem: B[k][n] at S[n*strideH + k] (k contiguous)
__device__ __forceinline__ void ldBh(u32* b, const __half* S, int strideH,
                                     int nc, int kc, int lane) {
    const u32* p = (const u32*)(S + (nc + (lane >> 2)) * strideH + kc) + (lane & 3);
    b[0] = p[0]; b[1] = p[4];
}

// ---------------- repack: f32 weights -> fragment-order half2 ----------------
__global__ void repack_kernel(const float* __restrict__ qkv_w,
                              const float* __restrict__ trans_w,
                              const float* __restrict__ tx,
                              const float* __restrict__ ty,
                              const float* __restrict__ tz)
{
    int e = blockIdx.x * TPB + threadIdx.x;
    if (e < 49152) {                                    // qkv
        int qq = e & 3, lane = (e >> 2) & 31;
        int f = e >> 7;
        int p   = f % 3;  f /= 3;
        int w   = f % 8;  f /= 8;
        int k16 = f % 8;
        int st  = f / 8;
        int tile = p * 2 + (qq >> 1), breg = qq & 1;
        int col  = w * 48 + tile * 8 + (lane >> 2);
        int krow = k16 * 16 + 2 * (lane & 3) + 8 * breg;
        const float* W = qkv_w + st * 49152;
        qkvR[e] = packh(W[krow * 384 + col], W[(krow + 1) * 384 + col]);
    } else if (e < 73728) {                             // trans
        int e2 = e - 49152;
        int qq = e2 & 3, lane = (e2 >> 2) & 31;
        int f = e2 >> 7;
        int w   = f % 8;  f /= 8;
        int k16 = f % 8;
        int blk = f / 8;
        int j = qq >> 1, breg = qq & 1;
        int col  = w * 16 + j * 8 + (lane >> 2);
        int krow = k16 * 16 + 2 * (lane & 3) + 8 * breg;
        const float* W = trans_w + blk * 16384;
        trR[e2] = packh(W[krow * 128 + col], W[(krow + 1) * 128 + col]);
    } else if (e < 95232) {                             // tables
        int e3 = e - 73728;
        int qq = e3 & 1, lane = (e3 >> 1) & 31;
        int f = e3 >> 6;
        int n   = f % 7;  f /= 7;
        int k16 = f % 8;  f /= 8;
        int t   = f % 3;
        int st  = f / 3;
        const float* T = (t == 0 ? tx : (t == 1 ? ty : tz)) + (st * 3 + 1) * L_ * D_;
        int nn = n * 8 + (lane >> 2);       // <=55, in-bounds of table alloc; never indexed >49
        int kk = k16 * 16 + 2 * (lane & 3) + 8 * qq;
        tbR[e3] = packh(T[nn * D_ + kk], T[nn * D_ + kk + 1]);
    }
}

// ---------------- shared memory (~60 KB -> 3 CTAs/SM) ----------------
struct __align__(16) Smem {
    float  Pf[3 * K_ * SP];  // P f32 [3][32][52]; first 8704B alias X/FO half[32][136]; H at end
    __half q [K_ * SX];      // fp16
    __half k [K_ * SX];      // fp16
    __half vT[D_ * SV];      // v transposed [d][j], fp16
    float  sc[K_ * SSC];     // raw scores f32
    __half at[K_ * SA];      // attn fp16
    int    idxp[K_][K_];     // packed quant indices (stage 0 -> stage 1)
    float  cx[K_], cy[K_], cz[K_];
    float  pooled[D_];
    int    gidx[K_];
};

// ht += X @ W-block (repacked half2); warp w owns cols [16w,16w+16)
__device__ __forceinline__ void trans_mma(const __half* __restrict__ X,
                                          const u32* __restrict__ Rb,
                                          float ht[2][2][4], int w, int lane)
{
#pragma unroll
    for (int k16 = 0; k16 < 8; k16++) {
        uint4 vv = *(const uint4*)(Rb + ((k16 * 8 + w) << 7) + lane * 4);
        u32 b0[2] = {vv.x, vv.y}, b1[2] = {vv.z, vv.w};
        u32 a0[4], a1[4];
        ldsmA(a0, X, SX, 0,  k16 * 16, lane);
        ldsmA(a1, X, SX, 16, k16 * 16, lane);
        mma16(ht[0][0], a0, b0); mma16(ht[1][0], a1, b0);
        mma16(ht[0][1], a0, b1); mma16(ht[1][1], a1, b1);
    }
}

// one qkv column pass: j-tiles [J0, J0+JN) of warp w's 6 (uint4-block B loads)
template<int J0, int JN>
__device__ __forceinline__ void qkv_pass(Smem& s, const __half* __restrict__ XU,
                                         const float* __restrict__ bb,
                                         int st, int w, int lane)
{
    const int nw = w * 48;
    float c[2][JN][4];
#pragma unroll
    for (int j = 0; j < JN; j++) {
        float b0 = bb[nw + (J0 + j) * 8 + 2 * (lane & 3)];
        float b1 = bb[nw + (J0 + j) * 8 + 2 * (lane & 3) + 1];
        c[0][j][0] = b0; c[0][j][1] = b1; c[0][j][2] = b0; c[0][j][3] = b1;
        c[1][j][0] = b0; c[1][j][1] = b1; c[1][j][2] = b0; c[1][j][3] = b1;
    }
#pragma unroll
    for (int k16 = 0; k16 < 8; k16++) {
        const u32* rp = qkvR + (((st * 8 + k16) * 8 + w) * 3) * 128 + lane * 4;
        u32 bv[JN][2];
#pragma unroll
        for (int jj = 0; jj < JN / 2; jj++) {
            uint4 v = *(const uint4*)(rp + ((J0 / 2) + jj) * 128);
            bv[2 * jj][0] = v.x;     bv[2 * jj][1] = v.y;
            bv[2 * jj + 1][0] = v.z; bv[2 * jj + 1][1] = v.w;
        }
        u32 a0[4], a1[4];
        ldsmA(a0, XU, SX, 0,  k16 * 16, lane);
        ldsmA(a1, XU, SX, 16, k16 * 16, lane);
#pragma unroll
        for (int j = 0; j < JN; j++) {
            mma16(c[0][j], a0, bv[j]);
            mma16(c[1][j], a1, bv[j]);
        }
    }
    // writeback fp16: cols 0-127 -> q, 128-255 -> k, 256-383 -> vT (transposed)
#pragma unroll
    for (int m = 0; m < 2; m++)
#pragma unroll
        for (int j = 0; j < JN; j++) {
            int col = nw + (J0 + j) * 8 + 2 * (lane & 3);
            int row = (lane >> 2) + m * 16;
            float* c4 = c[m][j];
            if (col < 128) {
                *(u32*)(s.q + row * SX + col)       = packh(c4[0], c4[1]);
                *(u32*)(s.q + (row + 8) * SX + col) = packh(c4[2], c4[3]);
            } else if (col < 256) {
                int cc = col - 128;
                *(u32*)(s.k + row * SX + cc)        = packh(c4[0], c4[1]);
                *(u32*)(s.k + (row + 8) * SX + cc)  = packh(c4[2], c4[3]);
            } else {
                int cc = col - 256;
                s.vT[cc * SV + row]           = __float2half_rn(c4[0]);
                s.vT[(cc + 1) * SV + row]     = __float2half_rn(c4[1]);
                s.vT[cc * SV + row + 8]       = __float2half_rn(c4[2]);
                s.vT[(cc + 1) * SV + row + 8] = __float2half_rn(c4[3]);
            }
        }
}

__global__ void __launch_bounds__(TPB, 3)
voxel_encoder_kernel(const float* __restrict__ inputs,
                     const float* __restrict__ coordinates,
                     const float* __restrict__ qkv_b,
                     const float* __restrict__ trans_b,
                     const float* __restrict__ ln_g,
                     const float* __restrict__ ln_b,
                     const int*   __restrict__ groups,
                     float* __restrict__ out,
                     float* __restrict__ ret)
{
    extern __shared__ __align__(16) char smem_raw[];
    Smem& s = *reinterpret_cast<Smem*>(smem_raw);

    const int tid  = threadIdx.x;
    const int w    = tid >> 5;
    const int lane = tid & 31;
    const int bg   = blockIdx.x;
    const int b    = bg / G_;
    const int g    = bg % G_;
    const int c0   = lane * 4;

    __half* XU = (__half*)s.Pf;               // X / FO overlay P region
    float*  P0 = s.Pf;
    float*  P1 = s.Pf + K_ * SP;
    float*  P2 = s.Pf + 2 * K_ * SP;

    // ---- gather indices + coordinates ----
    if (tid < K_) {
        int p = groups[bg * K_ + tid];
        s.gidx[tid] = p;
        const float* c = coordinates + ((long long)b * N_ + p) * 3;
        s.cx[tid] = c[0]; s.cy[tid] = c[1]; s.cz[tid] = c[2];
    }
    __syncthreads();

    // ---- gather features -> XU as fp16 ----
#pragma unroll
    for (int rr = 0; rr < 4; rr++) {
        int e = tid + TPB * rr;
        int row = e >> 5, c4 = e & 31;
        float4 val = *(const float4*)(inputs + ((long long)b * N_ + s.gidx[row]) * D_ + c4 * 4);
        uint2 hv; hv.x = packh(val.x, val.y); hv.y = packh(val.z, val.w);
        *(uint2*)(XU + row * SX + c4 * 4) = hv;
    }
    __syncthreads();

    // ---- trans accumulator in registers: warp w cols [16w,16w+16) ----
    float ht[2][2][4];
#pragma unroll
    for (int j = 0; j < 2; j++) {
        int col = w * 16 + j * 8 + 2 * (lane & 3);
        float b0 = trans_b[col], b1 = trans_b[col + 1];
        ht[0][j][0] = b0; ht[0][j][1] = b1; ht[0][j][2] = b0; ht[0][j][3] = b1;
        ht[1][j][0] = b0; ht[1][j][1] = b1; ht[1][j][2] = b0; ht[1][j][3] = b1;
    }

    trans_mma(XU, trR, ht, w, lane);     // ht += X @ W_block0 (raw features)

    // ================= attention stages =================
    for (int st = 0; st < S_; st++) {
        // ---------- qkv: two column passes (4 tiles + 2 tiles) ----------
        {
            const float* bb = qkv_b + st * 3 * D_;
            qkv_pass<0, 4>(s, XU, bb, st, w, lane);
            qkv_pass<4, 2>(s, XU, bb, st, w, lane);
            __syncthreads();
        }

        // ---------- P projections (warps 0-6) + scores (warp 7) ----------
        {
            if (w < 7) {
                float pc[3][2][4];
#pragma unroll
                for (int u = 0; u < 3; u++)
#pragma unroll
                    for (int m = 0; m < 2; m++)
#pragma unroll
                        for (int r = 0; r < 4; r++) pc[u][m][r] = 0.f;
#pragma unroll
                for (int k16 = 0; k16 < 8; k16++) {
                    u32 bv[3][2];
#pragma unroll
                    for (int u = 0; u < 3; u++) {
                        int tile = w * 3 + u;
                        int tt = tile / 7, n = tile % 7;
                        uint2 vv = *(const uint2*)(tbR +
                            ((((st * 3 + tt) * 8 + k16) * 7 + n) << 6) + lane * 2);
                        bv[u][0] = vv.x; bv[u][1] = vv.y;
                    }
                    u32 a0[4], a1[4];
                    ldsmA(a0, s.k, SX, 0,  k16 * 16, lane);
                    ldsmA(a1, s.k, SX, 16, k16 * 16, lane);
#pragma unroll
                    for (int u = 0; u < 3; u++) {
                        mma16(pc[u][0], a0, bv[u]);
                        mma16(pc[u][1], a1, bv[u]);
                    }
                }
#pragma unroll
                for (int u = 0; u < 3; u++) {
                    int tile = w * 3 + u;
                    int tt = tile / 7, nc = (tile % 7) * 8;
                    float* Pb = s.Pf + tt * K_ * SP;
                    int col = nc + 2 * (lane & 3);
                    bool ok = (col < SP - 1);        // clip tile 6 cols 52-55 (never read)
#pragma unroll
                    for (int m = 0; m < 2; m++) {
                        int row = (lane >> 2) + m * 16;
                        if (ok) {
                            *(ull*)&Pb[row * SP + col]       = pack2(pc[u][m][0], pc[u][m][1]);
                            *(ull*)&Pb[(row + 8) * SP + col] = pack2(pc[u][m][2], pc[u][m][3]);
                        }
                    }
                }
            } else {
                float scv[4][2][4];
#pragma unroll
                for (int n = 0; n < 4; n++)
#pragma unroll
                    for (int m = 0; m < 2; m++)
#pragma unroll
                        for (int r = 0; r < 4; r++) scv[n][m][r] = 0.f;
#pragma unroll
                for (int k16 = 0; k16 < 8; k16++) {
                    u32 a0[4], a1[4];
                    ldsmA(a0, s.q, SX, 0,  k16 * 16, lane);
                    ldsmA(a1, s.q, SX, 16, k16 * 16, lane);
#pragma unroll
                    for (int n = 0; n < 4; n++) {
                        u32 bv[2];
                        ldBh(bv, s.k, SX, n * 8, k16 * 16, lane);
                        mma16(scv[n][0], a0, bv);
                        mma16(scv[n][1], a1, bv);
                    }
                }
#pragma unroll
                for (int n = 0; n < 4; n++)
#pragma unroll
                    for (int m = 0; m < 2; m++) {
                        int col = n * 8 + 2 * (lane & 3);
                        int row = (lane >> 2) + m * 16;
                        *(ull*)&s.sc[row * SSC + col]       = pack2(scv[n][m][0], scv[n][m][1]);
                        *(ull*)&s.sc[(row + 8) * SSC + col] = pack2(scv[n][m][2], scv[n][m][3]);
                    }
            }
            __syncthreads();
        }

        // ---------- bias gather + softmax (warp w rows 4w..4w+3) ----------
        {
            const int i0 = w * 4;
            float cxj = s.cx[lane], cyj = s.cy[lane], czj = s.cz[lane];
#pragma unroll
            for (int r = 0; r < 4; r++) {
                int i = i0 + r;
                int ix, iy, iz;
                if (st == 0) {
                    float dx = s.cx[i] - cxj;
                    float dy = s.cy[i] - cyj;
                    float dz = s.cz[i] - czj;
                    ix = min(max((int)floorf((dx + 0.25f) / 0.01f), 0), L_ - 1);
                    iy = min(max((int)floorf((dy + 0.25f) / 0.01f), 0), L_ - 1);
                    iz = min(max((int)floorf((dz + 0.25f) / 0.01f), 0), L_ - 1);
                    s.idxp[i][lane] = ix | (iy << 8) | (iz << 16);
                } else {
                    int pk = s.idxp[i][lane];
                    ix = pk & 255; iy = (pk >> 8) & 255; iz = (pk >> 16) & 255;
                }
                float scr = (s.sc[i * SSC + lane]
                             + P0[i * SP + ix] + P1[i * SP + iy] + P2[i * SP + iz])
                            * 0.08838834764831843f;   // 1/sqrt(128)
                float mx = scr;
#pragma unroll
                for (int o = 16; o; o >>= 1) mx = fmaxf(mx, __shfl_xor_sync(0xffffffffu, mx, o));
                float e = __expf(scr - mx);
                float sum = e;
#pragma unroll
                for (int o = 16; o; o >>= 1) sum += __shfl_xor_sync(0xffffffffu, sum, o);
                s.at[i * SA + lane] = __float2half_rn(e * (1.0f / sum));
            }
        }
        __syncthreads();

        // ---------- f = attn @ v -> XU (next-stage X / final f2) ----------
        {
            float fc[2][2][4];
#pragma unroll
            for (int m = 0; m < 2; m++)
#pragma unroll
                for (int j = 0; j < 2; j++)
#pragma unroll
                    for (int r = 0; r < 4; r++) fc[m][j][r] = 0.f;
#pragma unroll
            for (int k16 = 0; k16 < 2; k16++) {
                int kc = k16 * 16;
                u32 a0[4], a1[4];
                ldsmA(a0, s.at, SA, 0,  kc, lane);
                ldsmA(a1, s.at, SA, 16, kc, lane);
#pragma unroll
                for (int j = 0; j < 2; j++) {
                    u32 bv[2];
                    ldBh(bv, s.vT, SV, w * 16 + j * 8, kc, lane);
                    mma16(fc[0][j], a0, bv);
                    mma16(fc[1][j], a1, bv);
                }
            }
#pragma unroll
            for (int m = 0; m < 2; m++)
#pragma unroll
                for (int j = 0; j < 2; j++) {
                    int col = w * 16 + j * 8 + 2 * (lane & 3);
                    int row = (lane >> 2) + m * 16;
                    *(u32*)(XU + row * SX + col)       = packh(fc[m][j][0], fc[m][j][1]);
                    *(u32*)(XU + (row + 8) * SX + col) = packh(fc[m][j][2], fc[m][j][3]);
                }
        }
        __syncthreads();

        // ---------- trans block st+1 ----------
        trans_mma(XU, trR + (st + 1) * 8 * 8 * 128, ht, w, lane);
        __syncthreads();
    }

    // ---- dump trans accumulator f32 -> H (reuse P region; X dead) ----
    float* H = s.Pf;
#pragma unroll
    for (int m = 0; m < 2; m++)
#pragma unroll
        for (int j = 0; j < 2; j++) {
            int col = w * 16 + j * 8 + 2 * (lane & 3);
            int row = (lane >> 2) + m * 16;
            *(ull*)&H[row * 128 + col]       = pack2(ht[m][j][0], ht[m][j][1]);
            *(ull*)&H[(row + 8) * 128 + col] = pack2(ht[m][j][2], ht[m][j][3]);
        }
    __syncthreads();

    // ================= LayerNorm + ReLU =================
    {
        const int i0 = w * 4;
        float4 g4 = *(const float4*)(ln_g + c0);
        float4 b4 = *(const float4*)(ln_b + c0);
#pragma unroll
        for (int r = 0; r < 4; r++) {
            int i = i0 + r;
            float4 h = *(const float4*)&H[i * 128 + c0];
            float s1 = h.x + h.y + h.z + h.w;
            float s2 = h.x * h.x + h.y * h.y + h.z * h.z + h.w * h.w;
#pragma unroll
            for (int o = 16; o; o >>= 1) {
                s1 += __shfl_xor_sync(0xffffffffu, s1, o);
                s2 += __shfl_xor_sync(0xffffffffu, s2, o);
            }
            float mu   = s1 * (1.0f / 128.0f);
            float var  = s2 * (1.0f / 128.0f) - mu * mu;
            float rstd = rsqrtf(var + 1e-5f);
            h.x = fmaxf((h.x - mu) * rstd * g4.x + b4.x, 0.0f);
            h.y = fmaxf((h.y - mu) * rstd * g4.y + b4.y, 0.0f);
            h.z = fmaxf((h.z - mu) * rstd * g4.z + b4.z, 0.0f);
            h.w = fmaxf((h.w - mu) * rstd * g4.w + b4.w, 0.0f);
            *(float4*)&H[i * 128 + c0] = h;
        }
    }
    __syncthreads();

    // ================= max-pool + outputs =================
    if (tid < D_) {
        float m = H[tid];
#pragma unroll
        for (int i = 1; i < K_; i++) m = fmaxf(m, H[i * 128 + tid]);
        s.pooled[tid] = m;
        int mm = g >> 6, nn = (g >> 3) & 7, tt = g & 7;
        int p = (tt << 6) + (nn << 3) + mm;          // transpose(0,3,2,1,4)
        out[((long long)b * G_ + p) * D_ + tid] = m;
    }
    __syncthreads();

#pragma unroll
    for (int rr = 0; rr < 4; rr++) {
        int e = tid + TPB * rr;
        int row = e >> 5, c4 = e & 31;
        float4 val = *(const float4*)&s.pooled[c4 * 4];
        *(float4*)(ret + ((long long)b * N_ + s.gidx[row]) * D_ + c4 * 4) = val;
    }
}

extern "C" void kernel_launch(void* const* d_in, const int* in_sizes, int n_in,
                              void* d_out, int out_size)
{
    const float* inputs      = (const float*)d_in[0];
    const float* coordinates = (const float*)d_in[1];
    const float* qkv_w       = (const float*)d_in[2];
    const float* qkv_b       = (const float*)d_in[3];
    const float* table_x     = (const float*)d_in[4];
    const float* table_y     = (const float*)d_in[5];
    const float* table_z     = (const float*)d_in[6];
    const float* trans_w     = (const float*)d_in[7];
    const float* trans_b     = (const float*)d_in[8];
    const float* ln_g        = (const float*)d_in[9];
    const float* ln_b        = (const float*)d_in[10];
    const int*   groups      = (const int*)d_in[11];

    float* out = (float*)d_out;                      // [B, 512, 128]
    float* ret = out + (size_t)B_ * G_ * D_;         // [B, 16384, 128]

    repack_kernel<<<(95232 + TPB - 1) / TPB, TPB>>>(
        qkv_w, trans_w, table_x, table_y, table_z);

    cudaFuncSetAttribute(voxel_encoder_kernel,
                         cudaFuncAttributeMaxDynamicSharedMemorySize,
                         (int)sizeof(Smem));

    voxel_encoder_kernel<<<B_ * G_, TPB, sizeof(Smem)>>>(
        inputs, coordinates, qkv_b, trans_b, ln_g, ln_b, groups, out, ret);
}